// round 16
// baseline (speedup 1.0000x reference)
#include <cuda_runtime.h>
#include <cuda_fp16.h>

#define NN 100000
#define EE 1600000
#define BB 64
#define EPS_MSG 1e-7f
#define SCAN_BLOCKS 98

// ---------------- scratch (static __device__, no allocations) ----------------
__device__ float  g_h[NN * 64];        // node state h (fp32)
__device__ __align__(16) __half g_outh[NN * 64];  // agg + residual, half (GEMM1 input)
__device__ __align__(16) __half g_hid[NN * 128];  // MLP hidden, half (also [N,12] for l0)
__device__ float  g_x8[NN * 8];        // relu(x)+eps padded to 8 (layer-0 messages)
__device__ int    g_deg[NN];           // zero at start; self-cleaned by k_scan
__device__ int    g_rowptr[NN + 1];
__device__ int    g_pos[NN];
__device__ int    g_col[EE];
__device__ unsigned long long g_lk[SCAN_BLOCKS];  // lookback: (status<<32)|sum; reset in k_deg
__device__ float  g_psum[2048 * 128];
__device__ float  g_psumsq[2048 * 128];
__device__ float  g_scale[128];
__device__ float  g_shift[128];
__device__ unsigned g_sch2[64];        // half2-packed BN scale pairs
__device__ unsigned g_shh2[64];        // half2-packed BN shift pairs
__device__ unsigned g_pool[BB * 64];   // zero = empty; self-cleaned by k_final
__device__ int    g_ctr;               // last-block counter (self-cleaning)
// pre-transposed half weights (built in k_deg): w1t[l][n=128][k pad 72]; w2t[l][n=64][k=128]
__device__ __align__(16) __half g_w1t[3][128 * 72];
__device__ __align__(16) __half g_w2t[3][64 * 128];

// ---------------- helpers ----------------
__device__ __forceinline__ unsigned encf(float f) {
    unsigned u = __float_as_uint(f);
    return (u & 0x80000000u) ? ~u : (u | 0x80000000u);
}
__device__ __forceinline__ float decf(unsigned u) {
    return __uint_as_float((u & 0x80000000u) ? (u ^ 0x80000000u) : ~u);
}
__device__ __forceinline__ void mma_f16(float* d, unsigned a0, unsigned a1,
                                        unsigned a2, unsigned a3,
                                        unsigned b0, unsigned b1) {
    asm volatile(
        "mma.sync.aligned.m16n8k16.row.col.f32.f16.f16.f32 "
        "{%0,%1,%2,%3}, {%4,%5,%6,%7}, {%8,%9}, {%0,%1,%2,%3};"
        : "+f"(d[0]), "+f"(d[1]), "+f"(d[2]), "+f"(d[3])
        : "r"(a0), "r"(a1), "r"(a2), "r"(a3), "r"(b0), "r"(b1));
}
__device__ __forceinline__ unsigned pack_h2(float a, float b) {
    __half2 h = __floats2half2_rn(a, b);
    return *(unsigned*)&h;
}
// bn+relu on a packed half2 (pure HFMA2/HMAX2, no conversions)
__device__ __forceinline__ unsigned bnrelu_h2(unsigned hv, unsigned sc, unsigned sh) {
    __half2 z = __float2half2_rn(0.f);
    __half2 r = __hmax2(__hfma2(*(__half2*)&hv, *(__half2*)&sc, *(__half2*)&sh), z);
    return *(unsigned*)&r;
}

// per-float4 message accumulate: relu+eps, exp, p/q update (channels kx..kx+3)
#define ACC4(v, kx)                                                             \
    do {                                                                        \
        float a, ex;                                                            \
        a = fmaxf((v).x, 0.f) + EPS_MSG; ex = __expf(a);                        \
        p[(kx)] += ex;     q[(kx)] = fmaf(a, ex, q[(kx)]);                      \
        a = fmaxf((v).y, 0.f) + EPS_MSG; ex = __expf(a);                        \
        p[(kx) + 1] += ex; q[(kx) + 1] = fmaf(a, ex, q[(kx) + 1]);              \
        a = fmaxf((v).z, 0.f) + EPS_MSG; ex = __expf(a);                        \
        p[(kx) + 2] += ex; q[(kx) + 2] = fmaf(a, ex, q[(kx) + 2]);              \
        a = fmaxf((v).w, 0.f) + EPS_MSG; ex = __expf(a);                        \
        p[(kx) + 3] += ex; q[(kx) + 3] = fmaf(a, ex, q[(kx) + 3]);              \
    } while (0)

// layer-0 per-edge accumulate from packed x8 (6 channels)
#define L0ACC(u0, u1)                                                            \
    do {                                                                         \
        float ex;                                                                \
        ex = __expf((u0).x); p[0] += ex; q[0] = fmaf((u0).x, ex, q[0]);          \
        ex = __expf((u0).y); p[1] += ex; q[1] = fmaf((u0).y, ex, q[1]);          \
        ex = __expf((u0).z); p[2] += ex; q[2] = fmaf((u0).z, ex, q[2]);          \
        ex = __expf((u0).w); p[3] += ex; q[3] = fmaf((u0).w, ex, q[3]);          \
        ex = __expf((u1).x); p[4] += ex; q[4] = fmaf((u1).x, ex, q[4]);          \
        ex = __expf((u1).y); p[5] += ex; q[5] = fmaf((u1).y, ex, q[5]);          \
    } while (0)

// ---------------- CSR degree + layer-0 messages + weight transpose + lk reset --------
__global__ void k_deg(const int* __restrict__ dst, const float* __restrict__ x,
                      const float* __restrict__ Lw1, const float* __restrict__ Lw2) {
    int e = blockIdx.x * blockDim.x + threadIdx.x;
    if (e < EE) atomicAdd(&g_deg[dst[e]], 1);
    if (e < NN) {
        float4 a, b;
        a.x = fmaxf(x[e * 6 + 0], 0.f) + EPS_MSG;
        a.y = fmaxf(x[e * 6 + 1], 0.f) + EPS_MSG;
        a.z = fmaxf(x[e * 6 + 2], 0.f) + EPS_MSG;
        a.w = fmaxf(x[e * 6 + 3], 0.f) + EPS_MSG;
        b.x = fmaxf(x[e * 6 + 4], 0.f) + EPS_MSG;
        b.y = fmaxf(x[e * 6 + 5], 0.f) + EPS_MSG;
        b.z = 0.f; b.w = 0.f;
        ((float4*)g_x8)[e * 2] = a;
        ((float4*)g_x8)[e * 2 + 1] = b;
    }
    if (e < SCAN_BLOCKS) g_lk[e] = 0ULL;   // reset lookback state for this replay
    // weight transpose + half conversion (once per launch, rides along)
    if (e < 3 * 128 * 64) {
        int l = e / (128 * 64);
        int r = e - l * (128 * 64);
        int n = r >> 6, k = r & 63;
        g_w1t[l][n * 72 + k] = __float2half(Lw1[l * 64 * 128 + k * 128 + n]);
    } else if (e < 2 * 3 * 128 * 64) {
        int j = e - 3 * 128 * 64;
        int l = j / (64 * 128);
        int r = j - l * (64 * 128);
        int n = r >> 7, k = r & 127;
        g_w2t[l][n * 128 + k] = __float2half(Lw2[l * 128 * 64 + k * 64 + n]);
    }
}

// single-pass scan (decoupled lookback) + apply + g_deg self-clean
__global__ void __launch_bounds__(1024) k_scan() {
    __shared__ int wsum[32];
    __shared__ int s_prefix;
    int t = threadIdx.x, bid = blockIdx.x;
    int idx = bid * 1024 + t;
    int lane = t & 31, wid = t >> 5;
    int d = (idx < NN) ? g_deg[idx] : 0;
    int s = d;
#pragma unroll
    for (int o = 1; o < 32; o <<= 1) {
        int a = __shfl_up_sync(0xffffffffu, s, o);
        if (lane >= o) s += a;
    }
    if (lane == 31) wsum[wid] = s;
    __syncthreads();
    if (wid == 0) {
        int w = wsum[lane];
#pragma unroll
        for (int o = 1; o < 32; o <<= 1) {
            int a = __shfl_up_sync(0xffffffffu, w, o);
            if (lane >= o) w += a;
        }
        wsum[lane] = w;
    }
    __syncthreads();
    s += (wid > 0) ? wsum[wid - 1] : 0;
    int total = wsum[31];

    if (t == 0) {
        if (bid == 0) {
            atomicExch(&g_lk[0], (2ULL << 32) | (unsigned)total);
            s_prefix = 0;
        } else {
            atomicExch(&g_lk[bid], (1ULL << 32) | (unsigned)total);
            int run = 0;
            int j = bid - 1;
            while (true) {
                unsigned long long v = atomicAdd(&g_lk[j], 0ULL);
                unsigned st = (unsigned)(v >> 32);
                if (st == 2u) { run += (int)(unsigned)v; break; }
                if (st == 1u) { run += (int)(unsigned)v; j--; }
            }
            atomicExch(&g_lk[bid], (2ULL << 32) | (unsigned)(run + total));
            s_prefix = run;
        }
    }
    __syncthreads();
    s += s_prefix;
    if (idx < NN) {
        g_rowptr[idx + 1] = s;
        g_pos[idx] = s - d;
        g_deg[idx] = 0;   // self-clean for next replay
    }
    if (idx == 0) g_rowptr[0] = 0;
}

__global__ void k_scatter(const int* __restrict__ src, const int* __restrict__ dst) {
    int e = blockIdx.x * blockDim.x + threadIdx.x;
    if (e >= EE) return;
    int p = atomicAdd(&g_pos[dst[e]], 1);
    g_col[p] = src[e];
}

// ---------------- layer 0: 4-lane/node agg(F=6) + MLP1 (6->12) + BN --------------------
__global__ void __launch_bounds__(256) k_l0(const float* __restrict__ x,
                                            const float* __restrict__ w1,
                                            const float* __restrict__ b1,
                                            const float* __restrict__ gam,
                                            const float* __restrict__ bet) {
    __shared__ float w_s[72];
    __shared__ float sacc[12], sacc2[12];
    __shared__ int isLast;
    int t = threadIdx.x;
    if (t < 72) w_s[t] = w1[t];
    if (t < 12) { sacc[t] = 0.f; sacc2[t] = 0.f; }
    __syncthreads();

    int gt = blockIdx.x * 256 + t;
    int n = gt >> 2, sub = gt & 3;
    float hid[12];
#pragma unroll
    for (int j = 0; j < 12; j++) hid[j] = 0.f;

    if (n < NN) {
        int beg = g_rowptr[n], end = g_rowptr[n + 1];
        float p[6], q[6];
#pragma unroll
        for (int c = 0; c < 6; c++) { p[c] = 0.f; q[c] = 0.f; }
        const float4* __restrict__ X8 = (const float4*)g_x8;
        int e = beg + sub;
        for (; e + 4 < end; e += 8) {  // 2 edges/lane/iter -> 4 LDG.128 in flight
            int s0 = g_col[e], s1 = g_col[e + 4];
            float4 u0 = X8[s0 * 2], u1 = X8[s0 * 2 + 1];
            float4 v0 = X8[s1 * 2], v1 = X8[s1 * 2 + 1];
            L0ACC(u0, u1);
            L0ACC(v0, v1);
        }
        for (; e < end; e += 4) {
            int s0 = g_col[e];
            float4 u0 = X8[s0 * 2], u1 = X8[s0 * 2 + 1];
            L0ACC(u0, u1);
        }
        // merge the 4 lanes of this node
#pragma unroll
        for (int c = 0; c < 6; c++) {
            p[c] += __shfl_xor_sync(0xffffffffu, p[c], 1);
            q[c] += __shfl_xor_sync(0xffffffffu, q[c], 1);
            p[c] += __shfl_xor_sync(0xffffffffu, p[c], 2);
            q[c] += __shfl_xor_sync(0xffffffffu, q[c], 2);
        }
        if (sub == 0) {
            float o[6];
#pragma unroll
            for (int c = 0; c < 6; c++) o[c] = q[c] / (p[c] + 1e-16f) + x[n * 6 + c];
#pragma unroll
            for (int j = 0; j < 12; j++) {
                float a = b1[j];
#pragma unroll
                for (int c = 0; c < 6; c++) a = fmaf(o[c], w_s[c * 12 + j], a);
                hid[j] = a;
                g_hid[n * 12 + j] = __float2half(a);
            }
        }
    }
    // BN partials: only sub==0 lanes contribute (others hold zeros)
#pragma unroll
    for (int j = 0; j < 12; j++) {
        float v = hid[j], v2 = v * v;
        for (int off = 16; off; off >>= 1) {
            v += __shfl_down_sync(0xffffffffu, v, off);
            v2 += __shfl_down_sync(0xffffffffu, v2, off);
        }
        if ((t & 31) == 0) { atomicAdd(&sacc[j], v); atomicAdd(&sacc2[j], v2); }
    }
    __syncthreads();
    if (t < 12) {
        g_psum[blockIdx.x * 12 + t] = sacc[t];
        g_psumsq[blockIdx.x * 12 + t] = sacc2[t];
    }
    __threadfence();
    if (t == 0) isLast = (atomicAdd(&g_ctr, 1) == (int)gridDim.x - 1);
    __syncthreads();
    if (isLast) {
        if (t == 0) g_ctr = 0;
        if (t < 12) {
            float s = 0.f, s2 = 0.f;
            for (int i = 0; i < (int)gridDim.x; i++) {
                s += g_psum[i * 12 + t];
                s2 += g_psumsq[i * 12 + t];
            }
            float mu = s / (float)NN;
            float var = fmaxf(s2 / (float)NN - mu * mu, 0.f);
            float sc = gam[t] * rsqrtf(var + 1e-5f);
            g_scale[t] = sc;
            g_shift[t] = bet[t] - mu * sc;
        }
    }
}

// ---------------- layer 0 MLP2: relu(bn(hid12)) @ w2[12,64] + b2 -> h = relu(.) ----------------
__global__ void __launch_bounds__(256) k_l0_mlp2(const float* __restrict__ w2,
                                                 const float* __restrict__ b2) {
    __shared__ float w_s[12 * 64];
    __shared__ float b_s[64];
    int t = threadIdx.x;
    for (int i = t; i < 768; i += 256) w_s[i] = w2[i];
    if (t < 64) b_s[t] = b2[t];
    __syncthreads();
    int n = blockIdx.x * 256 + t;
    if (n >= NN) return;
    float v[12];
#pragma unroll
    for (int j = 0; j < 12; j++)
        v[j] = fmaxf(fmaf(__half2float(g_hid[n * 12 + j]), g_scale[j], g_shift[j]), 0.f);
    for (int c0 = 0; c0 < 64; c0 += 4) {
        float a0 = b_s[c0], a1 = b_s[c0 + 1], a2 = b_s[c0 + 2], a3 = b_s[c0 + 3];
#pragma unroll
        for (int j = 0; j < 12; j++) {
            float vj = v[j];
            a0 = fmaf(vj, w_s[j * 64 + c0], a0);
            a1 = fmaf(vj, w_s[j * 64 + c0 + 1], a1);
            a2 = fmaf(vj, w_s[j * 64 + c0 + 2], a2);
            a3 = fmaf(vj, w_s[j * 64 + c0 + 3], a3);
        }
        float4 o;
        o.x = fmaxf(a0, 0.f); o.y = fmaxf(a1, 0.f);
        o.z = fmaxf(a2, 0.f); o.w = fmaxf(a3, 0.f);
        *(float4*)(g_h + n * 64 + c0) = o;
    }
}

// ---------------- aggregation, F=64: warp/node, single-pass; OUTPUT HALF --------------
__global__ void __launch_bounds__(256) k_agg64() {
    int gt = blockIdx.x * blockDim.x + threadIdx.x;
    int n = gt >> 5;
    if (n >= NN) return;
    int lane = gt & 31;
    int half = lane >> 4, li = lane & 15;
    int beg = g_rowptr[n], end = g_rowptr[n + 1];
    const float4* __restrict__ H = (const float4*)g_h;

    float p[4], q[4];
#pragma unroll
    for (int k = 0; k < 4; k++) { p[k] = 0.f; q[k] = 0.f; }

    int e = beg + half;
    for (; e + 2 < end; e += 4) {
        int i0 = g_col[e], i1 = g_col[e + 2];
        float4 v0 = H[(size_t)i0 * 16 + li];
        float4 v1 = H[(size_t)i1 * 16 + li];
        ACC4(v0, 0);
        ACC4(v1, 0);
    }
    for (; e < end; e += 2) {
        int i0 = g_col[e];
        float4 v0 = H[(size_t)i0 * 16 + li];
        ACC4(v0, 0);
    }
#pragma unroll
    for (int k = 0; k < 4; k++) {
        p[k] += __shfl_xor_sync(0xffffffffu, p[k], 16);
        q[k] += __shfl_xor_sync(0xffffffffu, q[k], 16);
    }
    if (half == 0) {
        float4 r = H[(size_t)n * 16 + li];
        uint2 o;
        o.x = pack_h2(q[0] / (p[0] + 1e-16f) + fmaxf(r.x, 0.f),
                      q[1] / (p[1] + 1e-16f) + fmaxf(r.y, 0.f));
        o.y = pack_h2(q[2] / (p[2] + 1e-16f) + fmaxf(r.z, 0.f),
                      q[3] / (p[3] + 1e-16f) + fmaxf(r.w, 0.f));
        *(uint2*)(g_outh + (size_t)n * 64 + li * 4) = o;
    }
}

// ---------------- GEMM1 (fp16 m16n8k16): g_outh[N,64] @ W1 + b -> g_hid (half)
__global__ void __launch_bounds__(256) k_gemm1(int layer,
                                               const float* __restrict__ bias,
                                               const float* __restrict__ gam,
                                               const float* __restrict__ bet) {
    __shared__ __align__(16) __half a_s[128 * 72];
    __shared__ __align__(16) __half w_s[128 * 72];   // [n][k]
    __shared__ int isLast;
    int t = threadIdx.x, lane = t & 31, warp = t >> 5;
    int q = lane & 3, g = lane >> 2;
    int row0 = blockIdx.x * 128;
    int n0w = warp * 16;

#pragma unroll
    for (int i = t; i < 1024; i += 256) {
        int r = i >> 3, kk = (i & 7) << 3;
        int row = row0 + r;
        uint4 u = make_uint4(0u, 0u, 0u, 0u);
        if (row < NN) u = *(const uint4*)(g_outh + (size_t)row * 64 + kk);
        *(uint4*)(a_s + r * 72 + kk) = u;
    }
    {
        const uint4* __restrict__ Wt = (const uint4*)g_w1t[layer];
        uint4* ws4 = (uint4*)w_s;
#pragma unroll
        for (int i = t; i < 1152; i += 256) ws4[i] = Wt[i];
    }
    __syncthreads();

    float acc[8][2][4];
#pragma unroll
    for (int i = 0; i < 8; i++)
#pragma unroll
        for (int j = 0; j < 2; j++)
#pragma unroll
            for (int k = 0; k < 4; k++) acc[i][j][k] = 0.f;

#pragma unroll
    for (int ks = 0; ks < 64; ks += 16) {
        unsigned b[2][2];
#pragma unroll
        for (int nt = 0; nt < 2; nt++) {
            int n = n0w + nt * 8 + g;
            b[nt][0] = *(unsigned*)(w_s + n * 72 + ks + 2 * q);
            b[nt][1] = *(unsigned*)(w_s + n * 72 + ks + 2 * q + 8);
        }
#pragma unroll
        for (int mt = 0; mt < 8; mt++) {
            int r = mt * 16 + g;
            unsigned a0 = *(unsigned*)(a_s + r * 72 + ks + 2 * q);
            unsigned a1 = *(unsigned*)(a_s + (r + 8) * 72 + ks + 2 * q);
            unsigned a2 = *(unsigned*)(a_s + r * 72 + ks + 2 * q + 8);
            unsigned a3 = *(unsigned*)(a_s + (r + 8) * 72 + ks + 2 * q + 8);
            mma_f16(acc[mt][0], a0, a1, a2, a3, b[0][0], b[0][1]);
            mma_f16(acc[mt][1], a0, a1, a2, a3, b[1][0], b[1][1]);
        }
    }

#pragma unroll
    for (int nt = 0; nt < 2; nt++) {
        int c = n0w + nt * 8 + 2 * q;
        float2 bv = *(const float2*)(bias + c);
        float s0 = 0.f, s1 = 0.f, s20 = 0.f, s21 = 0.f;
#pragma unroll
        for (int mt = 0; mt < 8; mt++) {
            int rA = row0 + mt * 16 + g, rB = rA + 8;
            float v0 = acc[mt][nt][0] + bv.x, v1 = acc[mt][nt][1] + bv.y;
            float v2 = acc[mt][nt][2] + bv.x, v3 = acc[mt][nt][3] + bv.y;
            if (rA < NN) {
                *(unsigned*)(g_hid + (size_t)rA * 128 + c) = pack_h2(v0, v1);
                s0 += v0; s20 = fmaf(v0, v0, s20);
                s1 += v1; s21 = fmaf(v1, v1, s21);
            }
            if (rB < NN) {
                *(unsigned*)(g_hid + (size_t)rB * 128 + c) = pack_h2(v2, v3);
                s0 += v2; s20 = fmaf(v2, v2, s20);
                s1 += v3; s21 = fmaf(v3, v3, s21);
            }
        }
#pragma unroll
        for (int off = 16; off >= 4; off >>= 1) {
            s0 += __shfl_down_sync(0xffffffffu, s0, off);
            s1 += __shfl_down_sync(0xffffffffu, s1, off);
            s20 += __shfl_down_sync(0xffffffffu, s20, off);
            s21 += __shfl_down_sync(0xffffffffu, s21, off);
        }
        if (lane < 4) {
            int cc = n0w + nt * 8 + 2 * lane;
            g_psum[blockIdx.x * 128 + cc] = s0;
            g_psum[blockIdx.x * 128 + cc + 1] = s1;
            g_psumsq[blockIdx.x * 128 + cc] = s20;
            g_psumsq[blockIdx.x * 128 + cc + 1] = s21;
        }
    }
    __threadfence();
    if (t == 0) isLast = (atomicAdd(&g_ctr, 1) == (int)gridDim.x - 1);
    __syncthreads();
    if (isLast) {
        float* s_f = (float*)a_s;  // scratch: scale[128], shift[128]
        if (t == 0) g_ctr = 0;
        if (t < 128) {
            float s = 0.f, s2 = 0.f;
            int nb = (int)gridDim.x;
#pragma unroll 4
            for (int i = 0; i < nb; i++) {
                s += g_psum[i * 128 + t];
                s2 += g_psumsq[i * 128 + t];
            }
            float mu = s / (float)NN;
            float var = fmaxf(s2 / (float)NN - mu * mu, 0.f);
            float sc = gam[t] * rsqrtf(var + 1e-5f);
            float sh = bet[t] - mu * sc;
            g_scale[t] = sc;
            g_shift[t] = sh;
            s_f[t] = sc;
            s_f[128 + t] = sh;
        }
        __syncthreads();
        if (t < 64) {
            g_sch2[t] = pack_h2(s_f[2 * t], s_f[2 * t + 1]);
            g_shh2[t] = pack_h2(s_f[128 + 2 * t], s_f[128 + 2 * t + 1]);
        }
    }
}

// ---------------- GEMM2 (fp16 m16n8k16): relu(bn_h2(g_hid)) @ W2 + b; h += .
__global__ void __launch_bounds__(256) k_gemm2(int layer,
                                               const float* __restrict__ bias) {
    __shared__ __align__(16) __half a_s[128 * 72];
    __shared__ __align__(16) __half w_s[64 * 72];    // [n][k-chunk]
    __shared__ unsigned sc_s[64], sh_s[64];
    int t = threadIdx.x, lane = t & 31, warp = t >> 5;
    int q = lane & 3, g = lane >> 2;
    int row0 = blockIdx.x * 128;
    int n0w = warp * 8;
    float acc[8][4];
#pragma unroll
    for (int i = 0; i < 8; i++)
#pragma unroll
        for (int k = 0; k < 4; k++) acc[i][k] = 0.f;

    if (t < 64) { sc_s[t] = g_sch2[t]; sh_s[t] = g_shh2[t]; }
    __syncthreads();

    const __half* __restrict__ Wt = g_w2t[layer];

    for (int kc = 0; kc < 128; kc += 64) {
#pragma unroll
        for (int i = t; i < 1024; i += 256) {
            int r = i >> 3, j = i & 7;
            int row = row0 + r;
            uint4 u = make_uint4(0u, 0u, 0u, 0u);
            if (row < NN) {
                u = *(const uint4*)(g_hid + (size_t)row * 128 + kc + j * 8);
                int ci = (kc + j * 8) >> 1;
                u.x = bnrelu_h2(u.x, sc_s[ci],     sh_s[ci]);
                u.y = bnrelu_h2(u.y, sc_s[ci + 1], sh_s[ci + 1]);
                u.z = bnrelu_h2(u.z, sc_s[ci + 2], sh_s[ci + 2]);
                u.w = bnrelu_h2(u.w, sc_s[ci + 3], sh_s[ci + 3]);
            }
            *(uint4*)(a_s + r * 72 + j * 8) = u;
        }
#pragma unroll
        for (int i = t; i < 512; i += 256) {
            int n = i >> 3, j = i & 7;
            *(uint4*)(w_s + n * 72 + j * 8) =
                *(const uint4*)(Wt + n * 128 + kc + j * 8);
        }
        __syncthreads();
#pragma unroll
        for (int ks = 0; ks < 64; ks += 16) {
            int n = n0w + g;
            unsigned b0 = *(unsigned*)(w_s + n * 72 + ks + 2 * q);
            unsigned b1 = *(unsigned*)(w_s + n * 72 + ks + 2 * q + 8);
#pragma unroll
            for (int mt = 0; mt < 8; mt++) {
                int r = mt * 16 + g;
                unsigned a0 = *(unsigned*)(a_s + r * 72 + ks + 2 * q);
                unsigned a1 = *(unsigned*)(a_s + (r + 8) * 72 + ks + 2 * q);
                unsigned a2 = *(unsigned*)(a_s + r * 72 + ks + 2 * q + 8);
                unsigned a3 = *(unsigned*)(a_s + (r + 8) * 72 + ks + 2 * q + 8);
                mma_f16(acc[mt], a0, a1, a2, a3, b0, b1);
            }
        }
        __syncthreads();
    }
    int c = n0w + 2 * q;
    float2 bv = *(const float2*)(bias + c);
#pragma unroll
    for (int mt = 0; mt < 8; mt++) {
        int rA = row0 + mt * 16 + g, rB = rA + 8;
        if (rA < NN) {
            float2 hv = *(float2*)(g_h + (size_t)rA * 64 + c);
            hv.x += acc[mt][0] + bv.x;
            hv.y += acc[mt][1] + bv.y;
            *(float2*)(g_h + (size_t)rA * 64 + c) = hv;
        }
        if (rB < NN) {
            float2 hv = *(float2*)(g_h + (size_t)rB * 64 + c);
            hv.x += acc[mt][2] + bv.x;
            hv.y += acc[mt][3] + bv.y;
            *(float2*)(g_h + (size_t)rB * 64 + c) = hv;
        }
    }
}

// ---------------- pool: vectorized run-length max (4 cols/thread) ----------------
__global__ void __launch_bounds__(256) k_pool(const int* __restrict__ batch) {
    int t = threadIdx.x;
    int cg = t & 15, sub = t >> 4;
    int n0 = blockIdx.x * 256 + sub * 16;
    float ninf = -__int_as_float(0x7f800000);
    float4 cur = make_float4(ninf, ninf, ninf, ninf);
    int curb = -1;
    for (int i = 0; i < 16; i++) {
        int n = n0 + i;
        if (n >= NN) break;
        int b = batch[n];
        if (b != curb) {
            if (curb >= 0) {
                atomicMax(&g_pool[curb * 64 + cg * 4 + 0], encf(cur.x));
                atomicMax(&g_pool[curb * 64 + cg * 4 + 1], encf(cur.y));
                atomicMax(&g_pool[curb * 64 + cg * 4 + 2], encf(cur.z));
                atomicMax(&g_pool[curb * 64 + cg * 4 + 3], encf(cur.w));
            }
            curb = b;
            cur = make_float4(ninf, ninf, ninf, ninf);
        }
        float4 v = *(const float4*)(g_h + (size_t)n * 64 + cg * 4);
        cur.x = fmaxf(cur.x, v.x);
        cur.y = fmaxf(cur.y, v.y);
        cur.z = fmaxf(cur.z, v.z);
        cur.w = fmaxf(cur.w, v.w);
    }
    if (curb >= 0) {
        atomicMax(&g_pool[curb * 64 + cg * 4 + 0], encf(cur.x));
        atomicMax(&g_pool[curb * 64 + cg * 4 + 1], encf(cur.y));
        atomicMax(&g_pool[curb * 64 + cg * 4 + 2], encf(cur.z));
        atomicMax(&g_pool[curb * 64 + cg * 4 + 3], encf(cur.w));
    }
}

// ---------------- final MLP: [64,64] -> relu -> [64,80]; self-cleans g_pool ----------------
__global__ void __launch_bounds__(256) k_final(const float* __restrict__ w1,
                                               const float* __restrict__ b1,
                                               const float* __restrict__ w2,
                                               const float* __restrict__ b2,
                                               float* __restrict__ out) {
    __shared__ float g_s[64 * 64];
    __shared__ float t_s[64 * 64];
    int t = threadIdx.x;
    for (int i = t; i < 4096; i += 256) {
        unsigned u = g_pool[i];
        g_s[i] = (u == 0u) ? 0.f : decf(u);
        g_pool[i] = 0u;  // self-clean for next replay
    }
    __syncthreads();
    for (int e = t; e < 4096; e += 256) {
        int r = e >> 6, c = e & 63;
        float a = b1[c];
        for (int k = 0; k < 64; k++) a = fmaf(g_s[r * 64 + k], w1[k * 64 + c], a);
        t_s[e] = fmaxf(a, 0.f);
    }
    __syncthreads();
    for (int e = t; e < 5120; e += 256) {
        int r = e / 80, c = e % 80;
        float a = b2[c];
        for (int k = 0; k < 64; k++) a = fmaf(t_s[r * 64 + k], w2[k * 80 + c], a);
        out[e] = a;
    }
}

// ---------------- launch ----------------
extern "C" void kernel_launch(void* const* d_in, const int* in_sizes, int n_in,
                              void* d_out, int out_size) {
    const float* x    = (const float*)d_in[0];
    const int*   ei   = (const int*)d_in[1];
    const int*   batch = (const int*)d_in[2];
    const float* cw1  = (const float*)d_in[3];
    const float* cb1  = (const float*)d_in[4];
    const float* cg1  = (const float*)d_in[5];
    const float* cbe1 = (const float*)d_in[6];
    const float* cw2  = (const float*)d_in[7];
    const float* cb2  = (const float*)d_in[8];
    const float* Lw1  = (const float*)d_in[9];
    const float* Lb1  = (const float*)d_in[10];
    const float* Lg1  = (const float*)d_in[11];
    const float* Lbe1 = (const float*)d_in[12];
    const float* Lw2  = (const float*)d_in[13];
    const float* Lb2  = (const float*)d_in[14];
    const float* mw1  = (const float*)d_in[15];
    const float* mb1  = (const float*)d_in[16];
    const float* mw2  = (const float*)d_in[17];
    const float* mb2  = (const float*)d_in[18];
    float* out = (float*)d_out;

    const int* src = ei;
    const int* dst = ei + EE;

    // CSR build + weight prep (g_deg starts zero; re-zeroed by k_scan each replay)
    k_deg<<<EE / 256, 256>>>(dst, x, Lw1, Lw2);
    k_scan<<<SCAN_BLOCKS, 1024>>>();
    k_scatter<<<EE / 256, 256>>>(src, dst);

    // layer 0 (6 -> 12 -> 64), h = relu(genconv(x))  [4 lanes per node]
    k_l0<<<1563, 256>>>(x, cw1, cb1, cg1, cbe1);
    k_l0_mlp2<<<391, 256>>>(cw2, cb2);

    // layers 1..3: h += genconv(relu(h))
    for (int i = 0; i < 3; i++) {
        k_agg64<<<12500, 256>>>();
        k_gemm1<<<782, 256>>>(i, Lb1 + i * 128, Lg1 + i * 128, Lbe1 + i * 128);
        k_gemm2<<<782, 256>>>(i, Lb2 + i * 64);
    }

    k_pool<<<391, 256>>>(batch);
    k_final<<<1, 256>>>(mw1, mb1, mw2, mb2, out);
}

// round 17
// speedup vs baseline: 1.1173x; 1.1173x over previous
#include <cuda_runtime.h>
#include <cuda_fp16.h>

#define NN 100000
#define EE 1600000
#define BB 64
#define EPS_MSG 1e-7f

// ---------------- scratch (static __device__, no allocations) ----------------
__device__ float  g_h[NN * 64];        // node state h (fp32)
__device__ __align__(16) __half g_outh[NN * 64];  // agg + residual, half (GEMM1 input)
__device__ __align__(16) __half g_hid[NN * 128];  // MLP hidden, half (also [N,12] for l0)
__device__ float  g_x8[NN * 8];        // relu(x)+eps padded to 8 (layer-0 messages)
__device__ int    g_deg[NN];           // zero at start; self-cleaned by k_scan3
__device__ int    g_tmp[NN];
__device__ int    g_rowptr[NN + 1];
__device__ int    g_pos[NN];
__device__ int    g_col[EE];
__device__ int    g_bsum[128];
__device__ float  g_psum[2048 * 128];
__device__ float  g_psumsq[2048 * 128];
__device__ float  g_scale[128];
__device__ float  g_shift[128];
__device__ unsigned g_sch2[64];        // half2-packed BN scale pairs
__device__ unsigned g_shh2[64];        // half2-packed BN shift pairs
__device__ unsigned g_pool[BB * 64];   // zero = empty; self-cleaned by k_final
__device__ int    g_ctr;               // last-block counter (self-cleaning)
// pre-transposed half weights (built in k_deg): w1t[l][n=128][k pad 72]; w2t[l][n=64][k=128]
__device__ __align__(16) __half g_w1t[3][128 * 72];
__device__ __align__(16) __half g_w2t[3][64 * 128];

// ---------------- helpers ----------------
__device__ __forceinline__ unsigned encf(float f) {
    unsigned u = __float_as_uint(f);
    return (u & 0x80000000u) ? ~u : (u | 0x80000000u);
}
__device__ __forceinline__ float decf(unsigned u) {
    return __uint_as_float((u & 0x80000000u) ? (u ^ 0x80000000u) : ~u);
}
__device__ __forceinline__ void mma_f16(float* d, unsigned a0, unsigned a1,
                                        unsigned a2, unsigned a3,
                                        unsigned b0, unsigned b1) {
    asm volatile(
        "mma.sync.aligned.m16n8k16.row.col.f32.f16.f16.f32 "
        "{%0,%1,%2,%3}, {%4,%5,%6,%7}, {%8,%9}, {%0,%1,%2,%3};"
        : "+f"(d[0]), "+f"(d[1]), "+f"(d[2]), "+f"(d[3])
        : "r"(a0), "r"(a1), "r"(a2), "r"(a3), "r"(b0), "r"(b1));
}
__device__ __forceinline__ unsigned pack_h2(float a, float b) {
    __half2 h = __floats2half2_rn(a, b);
    return *(unsigned*)&h;
}
// bn+relu on a packed half2 (pure HFMA2/HMAX2, no conversions)
__device__ __forceinline__ unsigned bnrelu_h2(unsigned hv, unsigned sc, unsigned sh) {
    __half2 z = __float2half2_rn(0.f);
    __half2 r = __hmax2(__hfma2(*(__half2*)&hv, *(__half2*)&sc, *(__half2*)&sh), z);
    return *(unsigned*)&r;
}

// per-float4 message accumulate: relu+eps, exp, p/q update (channels kx..kx+3)
#define ACC4(v, kx)                                                             \
    do {                                                                        \
        float a, ex;                                                            \
        a = fmaxf((v).x, 0.f) + EPS_MSG; ex = __expf(a);                        \
        p[(kx)] += ex;     q[(kx)] = fmaf(a, ex, q[(kx)]);                      \
        a = fmaxf((v).y, 0.f) + EPS_MSG; ex = __expf(a);                        \
        p[(kx) + 1] += ex; q[(kx) + 1] = fmaf(a, ex, q[(kx) + 1]);              \
        a = fmaxf((v).z, 0.f) + EPS_MSG; ex = __expf(a);                        \
        p[(kx) + 2] += ex; q[(kx) + 2] = fmaf(a, ex, q[(kx) + 2]);              \
        a = fmaxf((v).w, 0.f) + EPS_MSG; ex = __expf(a);                        \
        p[(kx) + 3] += ex; q[(kx) + 3] = fmaf(a, ex, q[(kx) + 3]);              \
    } while (0)

// layer-0 per-edge accumulate from packed x8 (6 channels)
#define L0ACC(u0, u1)                                                            \
    do {                                                                         \
        float ex;                                                                \
        ex = __expf((u0).x); p[0] += ex; q[0] = fmaf((u0).x, ex, q[0]);          \
        ex = __expf((u0).y); p[1] += ex; q[1] = fmaf((u0).y, ex, q[1]);          \
        ex = __expf((u0).z); p[2] += ex; q[2] = fmaf((u0).z, ex, q[2]);          \
        ex = __expf((u0).w); p[3] += ex; q[3] = fmaf((u0).w, ex, q[3]);          \
        ex = __expf((u1).x); p[4] += ex; q[4] = fmaf((u1).x, ex, q[4]);          \
        ex = __expf((u1).y); p[5] += ex; q[5] = fmaf((u1).y, ex, q[5]);          \
    } while (0)

// ---------------- CSR degree + layer-0 messages + weight transpose (fused) ----------
__global__ void k_deg(const int* __restrict__ dst, const float* __restrict__ x,
                      const float* __restrict__ Lw1, const float* __restrict__ Lw2) {
    int e = blockIdx.x * blockDim.x + threadIdx.x;
    if (e < EE) atomicAdd(&g_deg[dst[e]], 1);
    if (e < NN) {
        float4 a, b;
        a.x = fmaxf(x[e * 6 + 0], 0.f) + EPS_MSG;
        a.y = fmaxf(x[e * 6 + 1], 0.f) + EPS_MSG;
        a.z = fmaxf(x[e * 6 + 2], 0.f) + EPS_MSG;
        a.w = fmaxf(x[e * 6 + 3], 0.f) + EPS_MSG;
        b.x = fmaxf(x[e * 6 + 4], 0.f) + EPS_MSG;
        b.y = fmaxf(x[e * 6 + 5], 0.f) + EPS_MSG;
        b.z = 0.f; b.w = 0.f;
        ((float4*)g_x8)[e * 2] = a;
        ((float4*)g_x8)[e * 2 + 1] = b;
    }
    // weight transpose + half conversion (once per launch, rides along)
    if (e < 3 * 128 * 64) {
        int l = e / (128 * 64);
        int r = e - l * (128 * 64);
        int n = r >> 6, k = r & 63;
        g_w1t[l][n * 72 + k] = __float2half(Lw1[l * 64 * 128 + k * 128 + n]);
    } else if (e < 2 * 3 * 128 * 64) {
        int j = e - 3 * 128 * 64;
        int l = j / (64 * 128);
        int r = j - l * (64 * 128);
        int n = r >> 7, k = r & 127;
        g_w2t[l][n * 128 + k] = __float2half(Lw2[l * 128 * 64 + k * 64 + n]);
    }
}

// warp-shuffle block scan (2 syncs)
__global__ void __launch_bounds__(1024) k_scan1() {
    __shared__ int wsum[32];
    int t = threadIdx.x;
    int idx = blockIdx.x * 1024 + t;
    int lane = t & 31, wid = t >> 5;
    int s = (idx < NN) ? g_deg[idx] : 0;
#pragma unroll
    for (int o = 1; o < 32; o <<= 1) {
        int a = __shfl_up_sync(0xffffffffu, s, o);
        if (lane >= o) s += a;
    }
    if (lane == 31) wsum[wid] = s;
    __syncthreads();
    if (wid == 0) {
        int w = wsum[lane];
#pragma unroll
        for (int o = 1; o < 32; o <<= 1) {
            int a = __shfl_up_sync(0xffffffffu, w, o);
            if (lane >= o) w += a;
        }
        wsum[lane] = w;
    }
    __syncthreads();
    s += (wid > 0) ? wsum[wid - 1] : 0;
    if (idx < NN) g_tmp[idx] = s;
    if (t == 1023) g_bsum[blockIdx.x] = s;
}

// scan of 98 block sums fused into apply; self-cleans g_deg for next replay
__global__ void k_scan3() {
    __shared__ int s[128];
    int t = threadIdx.x;
    if (t < 128) s[t] = (t < 98) ? g_bsum[t] : 0;
    __syncthreads();
    for (int off = 1; off < 128; off <<= 1) {
        int a = (t >= off && t < 128) ? s[t - off] : 0;
        __syncthreads();
        if (t < 128) s[t] += a;
        __syncthreads();
    }
    int idx = blockIdx.x * blockDim.x + t;
    if (idx >= NN) return;
    int b = idx >> 10;
    int off = (b > 0) ? s[b - 1] : 0;
    int incl = g_tmp[idx] + off;
    g_rowptr[idx + 1] = incl;
    g_pos[idx] = incl - g_deg[idx];
    g_deg[idx] = 0;               // self-clean for next replay
    if (idx == 0) g_rowptr[0] = 0;
}

__global__ void k_scatter(const int* __restrict__ src, const int* __restrict__ dst) {
    int e = blockIdx.x * blockDim.x + threadIdx.x;
    if (e >= EE) return;
    int p = atomicAdd(&g_pos[dst[e]], 1);
    g_col[p] = src[e];
}

// ---------------- layer 0: serial/node agg(F=6), 4-edge unroll + MLP1 + BN ------------
__global__ void __launch_bounds__(256) k_l0(const float* __restrict__ x,
                                            const float* __restrict__ w1,
                                            const float* __restrict__ b1,
                                            const float* __restrict__ gam,
                                            const float* __restrict__ bet) {
    __shared__ float w_s[72];
    __shared__ float sacc[12], sacc2[12];
    __shared__ int isLast;
    int t = threadIdx.x;
    if (t < 72) w_s[t] = w1[t];
    if (t < 12) { sacc[t] = 0.f; sacc2[t] = 0.f; }
    __syncthreads();

    int n = blockIdx.x * 256 + t;
    float hid[12];
#pragma unroll
    for (int j = 0; j < 12; j++) hid[j] = 0.f;

    if (n < NN) {
        int beg = g_rowptr[n], end = g_rowptr[n + 1];
        float p[6], q[6];
#pragma unroll
        for (int c = 0; c < 6; c++) { p[c] = 0.f; q[c] = 0.f; }
        const float4* __restrict__ X8 = (const float4*)g_x8;
        int e = beg;
        for (; e + 3 < end; e += 4) {   // 4-edge unroll: 8 LDG.128 batched
            int s0 = g_col[e], s1 = g_col[e + 1], s2 = g_col[e + 2], s3 = g_col[e + 3];
            float4 a0 = X8[s0 * 2], a1 = X8[s0 * 2 + 1];
            float4 b0 = X8[s1 * 2], b1v = X8[s1 * 2 + 1];
            float4 c0 = X8[s2 * 2], c1 = X8[s2 * 2 + 1];
            float4 d0 = X8[s3 * 2], d1 = X8[s3 * 2 + 1];
            L0ACC(a0, a1);
            L0ACC(b0, b1v);
            L0ACC(c0, c1);
            L0ACC(d0, d1);
        }
        for (; e < end; e++) {
            int s = g_col[e];
            float4 v0 = X8[s * 2];
            float4 v1 = X8[s * 2 + 1];
            L0ACC(v0, v1);
        }
        float o[6];
#pragma unroll
        for (int c = 0; c < 6; c++) o[c] = q[c] / (p[c] + 1e-16f) + x[n * 6 + c];
#pragma unroll
        for (int j = 0; j < 12; j++) {
            float a = b1[j];
#pragma unroll
            for (int c = 0; c < 6; c++) a = fmaf(o[c], w_s[c * 12 + j], a);
            hid[j] = a;
            g_hid[n * 12 + j] = __float2half(a);
        }
    }
#pragma unroll
    for (int j = 0; j < 12; j++) {
        float v = hid[j], v2 = v * v;
        for (int off = 16; off; off >>= 1) {
            v += __shfl_down_sync(0xffffffffu, v, off);
            v2 += __shfl_down_sync(0xffffffffu, v2, off);
        }
        if ((t & 31) == 0) { atomicAdd(&sacc[j], v); atomicAdd(&sacc2[j], v2); }
    }
    __syncthreads();
    if (t < 12) {
        g_psum[blockIdx.x * 12 + t] = sacc[t];
        g_psumsq[blockIdx.x * 12 + t] = sacc2[t];
    }
    __threadfence();
    if (t == 0) isLast = (atomicAdd(&g_ctr, 1) == (int)gridDim.x - 1);
    __syncthreads();
    if (isLast) {
        if (t == 0) g_ctr = 0;
        if (t < 12) {
            float s = 0.f, s2 = 0.f;
            for (int i = 0; i < (int)gridDim.x; i++) {
                s += g_psum[i * 12 + t];
                s2 += g_psumsq[i * 12 + t];
            }
            float mu = s / (float)NN;
            float var = fmaxf(s2 / (float)NN - mu * mu, 0.f);
            float sc = gam[t] * rsqrtf(var + 1e-5f);
            g_scale[t] = sc;
            g_shift[t] = bet[t] - mu * sc;
        }
    }
}

// ---------------- layer 0 MLP2: relu(bn(hid12)) @ w2[12,64] + b2 -> h = relu(.) ----------------
__global__ void __launch_bounds__(256) k_l0_mlp2(const float* __restrict__ w2,
                                                 const float* __restrict__ b2) {
    __shared__ float w_s[12 * 64];
    __shared__ float b_s[64];
    int t = threadIdx.x;
    for (int i = t; i < 768; i += 256) w_s[i] = w2[i];
    if (t < 64) b_s[t] = b2[t];
    __syncthreads();
    int n = blockIdx.x * 256 + t;
    if (n >= NN) return;
    float v[12];
#pragma unroll
    for (int j = 0; j < 12; j++)
        v[j] = fmaxf(fmaf(__half2float(g_hid[n * 12 + j]), g_scale[j], g_shift[j]), 0.f);
    for (int c0 = 0; c0 < 64; c0 += 4) {
        float a0 = b_s[c0], a1 = b_s[c0 + 1], a2 = b_s[c0 + 2], a3 = b_s[c0 + 3];
#pragma unroll
        for (int j = 0; j < 12; j++) {
            float vj = v[j];
            a0 = fmaf(vj, w_s[j * 64 + c0], a0);
            a1 = fmaf(vj, w_s[j * 64 + c0 + 1], a1);
            a2 = fmaf(vj, w_s[j * 64 + c0 + 2], a2);
            a3 = fmaf(vj, w_s[j * 64 + c0 + 3], a3);
        }
        float4 o;
        o.x = fmaxf(a0, 0.f); o.y = fmaxf(a1, 0.f);
        o.z = fmaxf(a2, 0.f); o.w = fmaxf(a3, 0.f);
        *(float4*)(g_h + n * 64 + c0) = o;
    }
}

// ---------------- aggregation, F=64: warp/node, single-pass; OUTPUT HALF --------------
__global__ void __launch_bounds__(256) k_agg64() {
    int gt = blockIdx.x * blockDim.x + threadIdx.x;
    int n = gt >> 5;
    if (n >= NN) return;
    int lane = gt & 31;
    int half = lane >> 4, li = lane & 15;
    int beg = g_rowptr[n], end = g_rowptr[n + 1];
    const float4* __restrict__ H = (const float4*)g_h;

    float p[4], q[4];
#pragma unroll
    for (int k = 0; k < 4; k++) { p[k] = 0.f; q[k] = 0.f; }

    int e = beg + half;
    for (; e + 2 < end; e += 4) {
        int i0 = g_col[e], i1 = g_col[e + 2];
        float4 v0 = H[(size_t)i0 * 16 + li];
        float4 v1 = H[(size_t)i1 * 16 + li];
        ACC4(v0, 0);
        ACC4(v1, 0);
    }
    for (; e < end; e += 2) {
        int i0 = g_col[e];
        float4 v0 = H[(size_t)i0 * 16 + li];
        ACC4(v0, 0);
    }
#pragma unroll
    for (int k = 0; k < 4; k++) {
        p[k] += __shfl_xor_sync(0xffffffffu, p[k], 16);
        q[k] += __shfl_xor_sync(0xffffffffu, q[k], 16);
    }
    if (half == 0) {
        float4 r = H[(size_t)n * 16 + li];
        uint2 o;
        o.x = pack_h2(q[0] / (p[0] + 1e-16f) + fmaxf(r.x, 0.f),
                      q[1] / (p[1] + 1e-16f) + fmaxf(r.y, 0.f));
        o.y = pack_h2(q[2] / (p[2] + 1e-16f) + fmaxf(r.z, 0.f),
                      q[3] / (p[3] + 1e-16f) + fmaxf(r.w, 0.f));
        *(uint2*)(g_outh + (size_t)n * 64 + li * 4) = o;
    }
}

// ---------------- GEMM1 (fp16 m16n8k16): g_outh[N,64] @ W1 + b -> g_hid (half)
__global__ void __launch_bounds__(256) k_gemm1(int layer,
                                               const float* __restrict__ bias,
                                               const float* __restrict__ gam,
                                               const float* __restrict__ bet) {
    __shared__ __align__(16) __half a_s[128 * 72];
    __shared__ __align__(16) __half w_s[128 * 72];   // [n][k]
    __shared__ int isLast;
    int t = threadIdx.x, lane = t & 31, warp = t >> 5;
    int q = lane & 3, g = lane >> 2;
    int row0 = blockIdx.x * 128;
    int n0w = warp * 16;

#pragma unroll
    for (int i = t; i < 1024; i += 256) {
        int r = i >> 3, kk = (i & 7) << 3;
        int row = row0 + r;
        uint4 u = make_uint4(0u, 0u, 0u, 0u);
        if (row < NN) u = *(const uint4*)(g_outh + (size_t)row * 64 + kk);
        *(uint4*)(a_s + r * 72 + kk) = u;
    }
    {
        const uint4* __restrict__ Wt = (const uint4*)g_w1t[layer];
        uint4* ws4 = (uint4*)w_s;
#pragma unroll
        for (int i = t; i < 1152; i += 256) ws4[i] = Wt[i];
    }
    __syncthreads();

    float acc[8][2][4];
#pragma unroll
    for (int i = 0; i < 8; i++)
#pragma unroll
        for (int j = 0; j < 2; j++)
#pragma unroll
            for (int k = 0; k < 4; k++) acc[i][j][k] = 0.f;

#pragma unroll
    for (int ks = 0; ks < 64; ks += 16) {
        unsigned b[2][2];
#pragma unroll
        for (int nt = 0; nt < 2; nt++) {
            int n = n0w + nt * 8 + g;
            b[nt][0] = *(unsigned*)(w_s + n * 72 + ks + 2 * q);
            b[nt][1] = *(unsigned*)(w_s + n * 72 + ks + 2 * q + 8);
        }
#pragma unroll
        for (int mt = 0; mt < 8; mt++) {
            int r = mt * 16 + g;
            unsigned a0 = *(unsigned*)(a_s + r * 72 + ks + 2 * q);
            unsigned a1 = *(unsigned*)(a_s + (r + 8) * 72 + ks + 2 * q);
            unsigned a2 = *(unsigned*)(a_s + r * 72 + ks + 2 * q + 8);
            unsigned a3 = *(unsigned*)(a_s + (r + 8) * 72 + ks + 2 * q + 8);
            mma_f16(acc[mt][0], a0, a1, a2, a3, b[0][0], b[0][1]);
            mma_f16(acc[mt][1], a0, a1, a2, a3, b[1][0], b[1][1]);
        }
    }

#pragma unroll
    for (int nt = 0; nt < 2; nt++) {
        int c = n0w + nt * 8 + 2 * q;
        float2 bv = *(const float2*)(bias + c);
        float s0 = 0.f, s1 = 0.f, s20 = 0.f, s21 = 0.f;
#pragma unroll
        for (int mt = 0; mt < 8; mt++) {
            int rA = row0 + mt * 16 + g, rB = rA + 8;
            float v0 = acc[mt][nt][0] + bv.x, v1 = acc[mt][nt][1] + bv.y;
            float v2 = acc[mt][nt][2] + bv.x, v3 = acc[mt][nt][3] + bv.y;
            if (rA < NN) {
                *(unsigned*)(g_hid + (size_t)rA * 128 + c) = pack_h2(v0, v1);
                s0 += v0; s20 = fmaf(v0, v0, s20);
                s1 += v1; s21 = fmaf(v1, v1, s21);
            }
            if (rB < NN) {
                *(unsigned*)(g_hid + (size_t)rB * 128 + c) = pack_h2(v2, v3);
                s0 += v2; s20 = fmaf(v2, v2, s20);
                s1 += v3; s21 = fmaf(v3, v3, s21);
            }
        }
#pragma unroll
        for (int off = 16; off >= 4; off >>= 1) {
            s0 += __shfl_down_sync(0xffffffffu, s0, off);
            s1 += __shfl_down_sync(0xffffffffu, s1, off);
            s20 += __shfl_down_sync(0xffffffffu, s20, off);
            s21 += __shfl_down_sync(0xffffffffu, s21, off);
        }
        if (lane < 4) {
            int cc = n0w + nt * 8 + 2 * lane;
            g_psum[blockIdx.x * 128 + cc] = s0;
            g_psum[blockIdx.x * 128 + cc + 1] = s1;
            g_psumsq[blockIdx.x * 128 + cc] = s20;
            g_psumsq[blockIdx.x * 128 + cc + 1] = s21;
        }
    }
    __threadfence();
    if (t == 0) isLast = (atomicAdd(&g_ctr, 1) == (int)gridDim.x - 1);
    __syncthreads();
    if (isLast) {
        float* s_f = (float*)a_s;  // scratch: scale[128], shift[128]
        if (t == 0) g_ctr = 0;
        if (t < 128) {
            float s = 0.f, s2 = 0.f;
            int nb = (int)gridDim.x;
#pragma unroll 4
            for (int i = 0; i < nb; i++) {
                s += g_psum[i * 128 + t];
                s2 += g_psumsq[i * 128 + t];
            }
            float mu = s / (float)NN;
            float var = fmaxf(s2 / (float)NN - mu * mu, 0.f);
            float sc = gam[t] * rsqrtf(var + 1e-5f);
            float sh = bet[t] - mu * sc;
            g_scale[t] = sc;
            g_shift[t] = sh;
            s_f[t] = sc;
            s_f[128 + t] = sh;
        }
        __syncthreads();
        if (t < 64) {
            g_sch2[t] = pack_h2(s_f[2 * t], s_f[2 * t + 1]);
            g_shh2[t] = pack_h2(s_f[128 + 2 * t], s_f[128 + 2 * t + 1]);
        }
    }
}

// ---------------- GEMM2 (fp16 m16n8k16): relu(bn_h2(g_hid)) @ W2 + b; h += .
__global__ void __launch_bounds__(256) k_gemm2(int layer,
                                               const float* __restrict__ bias) {
    __shared__ __align__(16) __half a_s[128 * 72];
    __shared__ __align__(16) __half w_s[64 * 72];    // [n][k-chunk]
    __shared__ unsigned sc_s[64], sh_s[64];
    int t = threadIdx.x, lane = t & 31, warp = t >> 5;
    int q = lane & 3, g = lane >> 2;
    int row0 = blockIdx.x * 128;
    int n0w = warp * 8;
    float acc[8][4];
#pragma unroll
    for (int i = 0; i < 8; i++)
#pragma unroll
        for (int k = 0; k < 4; k++) acc[i][k] = 0.f;

    if (t < 64) { sc_s[t] = g_sch2[t]; sh_s[t] = g_shh2[t]; }
    __syncthreads();

    const __half* __restrict__ Wt = g_w2t[layer];

    for (int kc = 0; kc < 128; kc += 64) {
#pragma unroll
        for (int i = t; i < 1024; i += 256) {
            int r = i >> 3, j = i & 7;
            int row = row0 + r;
            uint4 u = make_uint4(0u, 0u, 0u, 0u);
            if (row < NN) {
                u = *(const uint4*)(g_hid + (size_t)row * 128 + kc + j * 8);
                int ci = (kc + j * 8) >> 1;
                u.x = bnrelu_h2(u.x, sc_s[ci],     sh_s[ci]);
                u.y = bnrelu_h2(u.y, sc_s[ci + 1], sh_s[ci + 1]);
                u.z = bnrelu_h2(u.z, sc_s[ci + 2], sh_s[ci + 2]);
                u.w = bnrelu_h2(u.w, sc_s[ci + 3], sh_s[ci + 3]);
            }
            *(uint4*)(a_s + r * 72 + j * 8) = u;
        }
#pragma unroll
        for (int i = t; i < 512; i += 256) {
            int n = i >> 3, j = i & 7;
            *(uint4*)(w_s + n * 72 + j * 8) =
                *(const uint4*)(Wt + n * 128 + kc + j * 8);
        }
        __syncthreads();
#pragma unroll
        for (int ks = 0; ks < 64; ks += 16) {
            int n = n0w + g;
            unsigned b0 = *(unsigned*)(w_s + n * 72 + ks + 2 * q);
            unsigned b1 = *(unsigned*)(w_s + n * 72 + ks + 2 * q + 8);
#pragma unroll
            for (int mt = 0; mt < 8; mt++) {
                int r = mt * 16 + g;
                unsigned a0 = *(unsigned*)(a_s + r * 72 + ks + 2 * q);
                unsigned a1 = *(unsigned*)(a_s + (r + 8) * 72 + ks + 2 * q);
                unsigned a2 = *(unsigned*)(a_s + r * 72 + ks + 2 * q + 8);
                unsigned a3 = *(unsigned*)(a_s + (r + 8) * 72 + ks + 2 * q + 8);
                mma_f16(acc[mt], a0, a1, a2, a3, b0, b1);
            }
        }
        __syncthreads();
    }
    int c = n0w + 2 * q;
    float2 bv = *(const float2*)(bias + c);
#pragma unroll
    for (int mt = 0; mt < 8; mt++) {
        int rA = row0 + mt * 16 + g, rB = rA + 8;
        if (rA < NN) {
            float2 hv = *(float2*)(g_h + (size_t)rA * 64 + c);
            hv.x += acc[mt][0] + bv.x;
            hv.y += acc[mt][1] + bv.y;
            *(float2*)(g_h + (size_t)rA * 64 + c) = hv;
        }
        if (rB < NN) {
            float2 hv = *(float2*)(g_h + (size_t)rB * 64 + c);
            hv.x += acc[mt][2] + bv.x;
            hv.y += acc[mt][3] + bv.y;
            *(float2*)(g_h + (size_t)rB * 64 + c) = hv;
        }
    }
}

// ---------------- pool: run-length max over sorted batch + encoded atomicMax ----------------
__global__ void __launch_bounds__(256) k_pool(const int* __restrict__ batch) {
    int t = threadIdx.x;
    int c = t & 63, sub = t >> 6;
    int n0 = blockIdx.x * 64 + sub * 16;
    float cur = -__int_as_float(0x7f800000);  // -inf
    int curb = -1;
    for (int i = 0; i < 16; i++) {
        int n = n0 + i;
        if (n >= NN) break;
        int b = batch[n];
        if (b != curb) {
            if (curb >= 0) atomicMax(&g_pool[curb * 64 + c], encf(cur));
            curb = b;
            cur = -__int_as_float(0x7f800000);
        }
        cur = fmaxf(cur, g_h[n * 64 + c]);
    }
    if (curb >= 0) atomicMax(&g_pool[curb * 64 + c], encf(cur));
}

// ---------------- final MLP: [64,64] -> relu -> [64,80]; self-cleans g_pool ----------------
__global__ void __launch_bounds__(256) k_final(const float* __restrict__ w1,
                                               const float* __restrict__ b1,
                                               const float* __restrict__ w2,
                                               const float* __restrict__ b2,
                                               float* __restrict__ out) {
    __shared__ float g_s[64 * 64];
    __shared__ float t_s[64 * 64];
    int t = threadIdx.x;
    for (int i = t; i < 4096; i += 256) {
        unsigned u = g_pool[i];
        g_s[i] = (u == 0u) ? 0.f : decf(u);
        g_pool[i] = 0u;  // self-clean for next replay
    }
    __syncthreads();
    for (int e = t; e < 4096; e += 256) {
        int r = e >> 6, c = e & 63;
        float a = b1[c];
        for (int k = 0; k < 64; k++) a = fmaf(g_s[r * 64 + k], w1[k * 64 + c], a);
        t_s[e] = fmaxf(a, 0.f);
    }
    __syncthreads();
    for (int e = t; e < 5120; e += 256) {
        int r = e / 80, c = e % 80;
        float a = b2[c];
        for (int k = 0; k < 64; k++) a = fmaf(t_s[r * 64 + k], w2[k * 80 + c], a);
        out[e] = a;
    }
}

// ---------------- launch ----------------
extern "C" void kernel_launch(void* const* d_in, const int* in_sizes, int n_in,
                              void* d_out, int out_size) {
    const float* x    = (const float*)d_in[0];
    const int*   ei   = (const int*)d_in[1];
    const int*   batch = (const int*)d_in[2];
    const float* cw1  = (const float*)d_in[3];
    const float* cb1  = (const float*)d_in[4];
    const float* cg1  = (const float*)d_in[5];
    const float* cbe1 = (const float*)d_in[6];
    const float* cw2  = (const float*)d_in[7];
    const float* cb2  = (const float*)d_in[8];
    const float* Lw1  = (const float*)d_in[9];
    const float* Lb1  = (const float*)d_in[10];
    const float* Lg1  = (const float*)d_in[11];
    const float* Lbe1 = (const float*)d_in[12];
    const float* Lw2  = (const float*)d_in[13];
    const float* Lb2  = (const float*)d_in[14];
    const float* mw1  = (const float*)d_in[15];
    const float* mb1  = (const float*)d_in[16];
    const float* mw2  = (const float*)d_in[17];
    const float* mb2  = (const float*)d_in[18];
    float* out = (float*)d_out;

    const int* src = ei;
    const int* dst = ei + EE;

    // CSR build + weight prep (g_deg starts zero; re-zeroed by k_scan3 each replay)
    k_deg<<<EE / 256, 256>>>(dst, x, Lw1, Lw2);
    k_scan1<<<98, 1024>>>();
    k_scan3<<<391, 256>>>();
    k_scatter<<<EE / 256, 256>>>(src, dst);

    // layer 0 (6 -> 12 -> 64), h = relu(genconv(x))
    k_l0<<<391, 256>>>(x, cw1, cb1, cg1, cbe1);
    k_l0_mlp2<<<391, 256>>>(cw2, cb2);

    // layers 1..3: h += genconv(relu(h))
    for (int i = 0; i < 3; i++) {
        k_agg64<<<12500, 256>>>();
        k_gemm1<<<782, 256>>>(i, Lb1 + i * 128, Lg1 + i * 128, Lbe1 + i * 128);
        k_gemm2<<<782, 256>>>(i, Lb2 + i * 64);
    }

    k_pool<<<1563, 256>>>(batch);
    k_final<<<1, 256>>>(mw1, mb1, mw2, mb2, out);
}